// round 1
// baseline (speedup 1.0000x reference)
#include <cuda_runtime.h>
#include <cuda_bf16.h>

#define NBLOCKS 2048
#define NTHREADS 256

// Scratch: one partial sum per block (fixed-order deterministic reduction).
__device__ float g_partials[NBLOCKS];

__device__ __forceinline__ float sample_loss(float l0, float l1, float l2,
                                             float t0, float t1, float t2,
                                             int h, float conf) {
    // adaptive temperature
    float T;
    if (conf > 0.9f)      T = 1.5f;
    else if (conf > 0.6f) T = 2.0f;
    else                  T = fminf(3.7f - 2.0f * conf, 3.0f);
    float invT = 1.0f / T;

    // KL(t || softmax(l/T)) = lse(l/T) + sum t*(log t - l/T)   (since sum t = 1)
    float s0 = l0 * invT, s1 = l1 * invT, s2 = l2 * invT;
    float m  = fmaxf(s0, fmaxf(s1, s2));
    float lse = m + __logf(__expf(s0 - m) + __expf(s1 - m) + __expf(s2 - m));
    float kl = lse;
    kl += (t0 > 0.0f) ? t0 * (__logf(t0) - s0) : 0.0f;
    kl += (t1 > 0.0f) ? t1 * (__logf(t1) - s1) : 0.0f;
    kl += (t2 > 0.0f) ? t2 * (__logf(t2) - s2) : 0.0f;

    // CE = lse(l) - l[hard]
    float m2   = fmaxf(l0, fmaxf(l1, l2));
    float lse2 = m2 + __logf(__expf(l0 - m2) + __expf(l1 - m2) + __expf(l2 - m2));
    float lh   = (h == 0) ? l0 : ((h == 1) ? l1 : l2);
    float ce   = lse2 - lh;

    return 0.5f * (kl + ce);   // ALPHA = 0.5
}

__global__ void __launch_bounds__(NTHREADS)
adl_reduce_kernel(const float4* __restrict__ logits4,
                  const int4*   __restrict__ hard4,
                  const float4* __restrict__ soft4,
                  const float4* __restrict__ conf4,
                  int ngroups /* = B/4 */) {
    float acc = 0.0f;
    const int stride = gridDim.x * blockDim.x;
    for (int g = blockIdx.x * blockDim.x + threadIdx.x; g < ngroups; g += stride) {
        // 4 samples -> 12 floats of logits / soft_labels = 3 float4 each
        const float4 L0 = logits4[3 * g + 0];
        const float4 L1 = logits4[3 * g + 1];
        const float4 L2 = logits4[3 * g + 2];
        const float4 S0 = soft4[3 * g + 0];
        const float4 S1 = soft4[3 * g + 1];
        const float4 S2 = soft4[3 * g + 2];
        const int4   H  = hard4[g];
        const float4 Cf = conf4[g];

        acc += sample_loss(L0.x, L0.y, L0.z, S0.x, S0.y, S0.z, H.x, Cf.x);
        acc += sample_loss(L0.w, L1.x, L1.y, S0.w, S1.x, S1.y, H.y, Cf.y);
        acc += sample_loss(L1.z, L1.w, L2.x, S1.z, S1.w, S2.x, H.z, Cf.z);
        acc += sample_loss(L2.y, L2.z, L2.w, S2.y, S2.z, S2.w, H.w, Cf.w);
    }

    // block reduction: warp shuffle then shared
    __shared__ float warp_sums[NTHREADS / 32];
    #pragma unroll
    for (int off = 16; off > 0; off >>= 1)
        acc += __shfl_down_sync(0xFFFFFFFFu, acc, off);
    if ((threadIdx.x & 31) == 0)
        warp_sums[threadIdx.x >> 5] = acc;
    __syncthreads();
    if (threadIdx.x < 32) {
        float v = (threadIdx.x < NTHREADS / 32) ? warp_sums[threadIdx.x] : 0.0f;
        #pragma unroll
        for (int off = 4; off > 0; off >>= 1)
            v += __shfl_down_sync(0xFFFFFFFFu, v, off);
        if (threadIdx.x == 0)
            g_partials[blockIdx.x] = v;
    }
}

__global__ void __launch_bounds__(256)
adl_finalize_kernel(float* __restrict__ out, int n_samples) {
    __shared__ double warp_sums[8];
    double acc = 0.0;
    for (int i = threadIdx.x; i < NBLOCKS; i += 256)
        acc += (double)g_partials[i];
    #pragma unroll
    for (int off = 16; off > 0; off >>= 1)
        acc += __shfl_down_sync(0xFFFFFFFFu, acc, off);
    if ((threadIdx.x & 31) == 0)
        warp_sums[threadIdx.x >> 5] = acc;
    __syncthreads();
    if (threadIdx.x == 0) {
        double s = 0.0;
        #pragma unroll
        for (int w = 0; w < 8; w++) s += warp_sums[w];
        out[0] = (float)(s / (double)n_samples);
    }
}

extern "C" void kernel_launch(void* const* d_in, const int* in_sizes, int n_in,
                              void* d_out, int out_size) {
    // metadata order: logits (B*3 f32), hard_labels (B i32), soft_labels (B*3 f32), confidences (B f32)
    const float4* logits4 = (const float4*)d_in[0];
    const int4*   hard4   = (const int4*)d_in[1];
    const float4* soft4   = (const float4*)d_in[2];
    const float4* conf4   = (const float4*)d_in[3];
    const int n = in_sizes[1];          // B
    const int ngroups = n / 4;          // B divisible by 4

    adl_reduce_kernel<<<NBLOCKS, NTHREADS>>>(logits4, hard4, soft4, conf4, ngroups);
    adl_finalize_kernel<<<1, 256>>>((float*)d_out, n);
}